// round 15
// baseline (speedup 1.0000x reference)
#include <cuda_runtime.h>
#include <cuda_fp16.h>
#include <mma.h>
#include <cstdint>

using namespace nvcuda;

// Problem constants
constexpr int NN = 100000;   // nodes
constexpr int NE = 1600000;  // edges
constexpr int NF = 128;      // input feats
constexpr int NC = 40;       // classes (post-projection feature width)
constexpr int NCP = 48;      // NC padded to 3x16 for wmma
constexpr int SLOT = 64;     // fixed per-node CSR slot (max deg ~36 for Poisson(16))

// ---------------- scratch (static device globals; no allocation) -------------
__device__ __align__(256) float  d_invdeg[NN];
__device__ __align__(256) float  d_dis[NN];
__device__ __align__(256) int    d_cur[NN];
__device__ __align__(256) int2   d_edat[(size_t)NN * SLOT];  // (row, raw ew bits)
__device__ __align__(256) __half d_Wh[NF * NCP];             // fp16 W, N-padded
__device__ __align__(256) __half d_hA[(size_t)NN * NC];      // fp16 intermediates
__device__ __align__(256) __half d_hB[(size_t)NN * NC];

// ---------------- kernels ----------------------------------------------------

__global__ void init_kernel() {
    int i = blockIdx.x * blockDim.x + threadIdx.x;
    if (i < NN) d_cur[i] = i * SLOT;
}

// convert W[128,40] fp32 -> d_Wh[128,48] fp16 (zero-padded cols)
__global__ void wconv_kernel(const float* __restrict__ W) {
    int i = blockIdx.x * blockDim.x + threadIdx.x;
    if (i < NF * NCP) {
        int k = i / NCP, c = i % NCP;
        d_Wh[i] = __float2half((c < NC) ? W[k * NC + c] : 0.0f);
    }
}

// fixed-slot CSR fill, 4 edges per thread: 4 independent atomic->store chains
// in flight hide the L2 atomic round-trip. NE % 4 == 0.
__global__ void fill_kernel(const int* __restrict__ row,
                            const int* __restrict__ col,
                            const float* __restrict__ ew) {
    int t = blockIdx.x * blockDim.x + threadIdx.x;
    if (t >= NE / 4) return;
    int4   r4 = reinterpret_cast<const int4*>(row)[t];
    int4   c4 = reinterpret_cast<const int4*>(col)[t];
    float4 w4 = reinterpret_cast<const float4*>(ew)[t];
    const int   r[4] = {r4.x, r4.y, r4.z, r4.w};
    const int   c[4] = {c4.x, c4.y, c4.z, c4.w};
    const float w[4] = {w4.x, w4.y, w4.z, w4.w};
    int pos[4];
    #pragma unroll
    for (int u = 0; u < 4; u++) {
        bool ok = (r[u] >= 0 && r[u] < NN && c[u] >= 0 && c[u] < NN);
        pos[u] = ok ? atomicAdd(&d_cur[c[u]], 1) : -1;
    }
    #pragma unroll
    for (int u = 0; u < 4; u++) {
        if (pos[u] >= 0 && pos[u] < (c[u] + 1) * SLOT)   // overflow guard
            d_edat[pos[u]] = make_int2(r[u], __float_as_int(w[u]));
    }
}

// weighted degree from each node's contiguous slot (vectorized int4 = 2 edges
// per load, unrolled for MLP); derive invdeg and dis.
__global__ void degsum_kernel() {
    int i = blockIdx.x * blockDim.x + threadIdx.x;
    if (i >= NN) return;
    int cnt = d_cur[i] - i * SLOT;
    if (cnt > SLOT) cnt = SLOT;
    const int4* p = reinterpret_cast<const int4*>(&d_edat[(size_t)i * SLOT]);
    float deg = 0.0f;
    int full = cnt >> 1;      // int4 = 2 edges
    int j = 0;
    for (; j + 4 <= full; j += 4) {
        int4 a = p[j], b = p[j+1], cc = p[j+2], d = p[j+3];
        deg += __int_as_float(a.y)  + __int_as_float(a.w)
             + __int_as_float(b.y)  + __int_as_float(b.w)
             + __int_as_float(cc.y) + __int_as_float(cc.w)
             + __int_as_float(d.y)  + __int_as_float(d.w);
    }
    for (; j < full; j++) {
        int4 a = p[j];
        deg += __int_as_float(a.y) + __int_as_float(a.w);
    }
    if (cnt & 1)
        deg += __int_as_float(d_edat[(size_t)i * SLOT + cnt - 1].y);
    bool pos = (deg > 0.0f);
    d_invdeg[i] = pos ? (1.0f / deg) : 0.0f;
    d_dis[i]    = pos ? rsqrtf(deg) : 0.0f;
}

// g0[NN,40] = fp16( dis * (x[NN,128] @ W[128,40]) )  via tensor cores.
__global__ void __launch_bounds__(128) xw_wmma(const float* __restrict__ x,
                                               __half* __restrict__ y) {
    __shared__ __half sx[64][136];   // x tile, fp16, ldm=136 (mult of 8)
    __shared__ __half sw[NF][NCP];   // W, fp16
    __shared__ float  sc[64][NCP];   // fp32 epilogue buffer
    int t = threadIdx.x;
    int warp = t >> 5;
    int nb = blockIdx.x * 64;

    for (int i = t; i < NF * NCP / 2; i += 128)
        reinterpret_cast<__half2*>(&sw[0][0])[i] =
            reinterpret_cast<const __half2*>(d_Wh)[i];

    for (int i = t; i < 64 * 32; i += 128) {
        int n = i >> 5, c4 = i & 31;
        int node = nb + n;
        float4 v = (node < NN)
                 ? reinterpret_cast<const float4*>(x + (size_t)node * NF)[c4]
                 : make_float4(0.f, 0.f, 0.f, 0.f);
        *reinterpret_cast<__half2*>(&sx[n][c4 * 4])     = __floats2half2_rn(v.x, v.y);
        *reinterpret_cast<__half2*>(&sx[n][c4 * 4 + 2]) = __floats2half2_rn(v.z, v.w);
    }
    __syncthreads();

    wmma::fragment<wmma::accumulator, 16, 16, 16, float> acc[3];
    #pragma unroll
    for (int j = 0; j < 3; j++) wmma::fill_fragment(acc[j], 0.0f);

    #pragma unroll
    for (int k = 0; k < NF / 16; k++) {
        wmma::fragment<wmma::matrix_a, 16, 16, 16, __half, wmma::row_major> a;
        wmma::load_matrix_sync(a, &sx[warp * 16][k * 16], 136);
        #pragma unroll
        for (int j = 0; j < 3; j++) {
            wmma::fragment<wmma::matrix_b, 16, 16, 16, __half, wmma::row_major> b;
            wmma::load_matrix_sync(b, &sw[k * 16][j * 16], NCP);
            wmma::mma_sync(acc[j], a, b, acc[j]);
        }
    }
    #pragma unroll
    for (int j = 0; j < 3; j++)
        wmma::store_matrix_sync(&sc[warp * 16][j * 16], acc[j], NCP,
                                wmma::mem_row_major);
    __syncthreads();

    for (int i = t; i < 64 * 20; i += 128) {
        int n = i / 20, c2 = i % 20;
        int node = nb + n;
        if (node < NN) {
            float sd = d_dis[node];   // g0 = D^{-1/2}(xW)
            __half2 h = __floats2half2_rn(sc[n][c2 * 2] * sd,
                                          sc[n][c2 * 2 + 1] * sd);
            reinterpret_cast<__half2*>(y + (size_t)node * NC)[c2] = h;
        }
    }
}

// Pull hop in g-space, fp16 -> fp16: g_next[c] = invdeg[c] * sum(ew * g[row]).
// 5-lane group per node (40 halves = 5 uint4), 6 nodes/warp, unroll-4 MLP.
__global__ void hop_h2h(const __half* __restrict__ hin,
                        __half* __restrict__ hout) {
    int gwarp = (blockIdx.x * blockDim.x + threadIdx.x) >> 5;
    int ln = threadIdx.x & 31;
    if (ln >= 30) return;
    int node = gwarp * 6 + ln / 5;
    if (node >= NN) return;
    int sub = ln % 5;

    int s = node * SLOT;
    int e = d_cur[node];
    if (e > s + SLOT) e = s + SLOT;

    float acc[8] = {};
    int i = s;
    for (; i + 4 <= e; i += 4) {
        int2 ed[4];
        uint4 v[4];
        #pragma unroll
        for (int u = 0; u < 4; u++) ed[u] = d_edat[i + u];
        #pragma unroll
        for (int u = 0; u < 4; u++)
            v[u] = __ldg(reinterpret_cast<const uint4*>(hin + (size_t)ed[u].x * NC) + sub);
        #pragma unroll
        for (int u = 0; u < 4; u++) {
            float w = __int_as_float(ed[u].y);
            const unsigned* p = &v[u].x;
            #pragma unroll
            for (int q = 0; q < 4; q++) {
                float2 f = __half22float2(*reinterpret_cast<const __half2*>(&p[q]));
                acc[2*q]   += f.x * w;
                acc[2*q+1] += f.y * w;
            }
        }
    }
    for (; i < e; i++) {
        int2 e0 = d_edat[i];
        float w = __int_as_float(e0.y);
        uint4 v0 = __ldg(reinterpret_cast<const uint4*>(hin + (size_t)e0.x * NC) + sub);
        const unsigned* p = &v0.x;
        #pragma unroll
        for (int q = 0; q < 4; q++) {
            float2 f = __half22float2(*reinterpret_cast<const __half2*>(&p[q]));
            acc[2*q]   += f.x * w;
            acc[2*q+1] += f.y * w;
        }
    }
    float idg = d_invdeg[node];      // destination-side D^{-1}
    uint4 o;
    unsigned* po = &o.x;
    #pragma unroll
    for (int q = 0; q < 4; q++) {
        __half2 h = __floats2half2_rn(acc[2*q] * idg, acc[2*q+1] * idg);
        po[q] = *reinterpret_cast<unsigned*>(&h);
    }
    *(reinterpret_cast<uint4*>(hout + (size_t)node * NC) + sub) = o;
}

// Final hop, fp16 -> fp32 d_out: out[c] = dis[c] * sum(ew * g[row]).
__global__ void hop_h2f(const __half* __restrict__ hin,
                        float* __restrict__ hout) {
    int gwarp = (blockIdx.x * blockDim.x + threadIdx.x) >> 5;
    int ln = threadIdx.x & 31;
    if (ln >= 30) return;
    int node = gwarp * 6 + ln / 5;
    if (node >= NN) return;
    int sub = ln % 5;

    int s = node * SLOT;
    int e = d_cur[node];
    if (e > s + SLOT) e = s + SLOT;

    float acc[8] = {};
    int i = s;
    for (; i + 4 <= e; i += 4) {
        int2 ed[4];
        uint4 v[4];
        #pragma unroll
        for (int u = 0; u < 4; u++) ed[u] = d_edat[i + u];
        #pragma unroll
        for (int u = 0; u < 4; u++)
            v[u] = __ldg(reinterpret_cast<const uint4*>(hin + (size_t)ed[u].x * NC) + sub);
        #pragma unroll
        for (int u = 0; u < 4; u++) {
            float w = __int_as_float(ed[u].y);
            const unsigned* p = &v[u].x;
            #pragma unroll
            for (int q = 0; q < 4; q++) {
                float2 f = __half22float2(*reinterpret_cast<const __half2*>(&p[q]));
                acc[2*q]   += f.x * w;
                acc[2*q+1] += f.y * w;
            }
        }
    }
    for (; i < e; i++) {
        int2 e0 = d_edat[i];
        float w = __int_as_float(e0.y);
        uint4 v0 = __ldg(reinterpret_cast<const uint4*>(hin + (size_t)e0.x * NC) + sub);
        const unsigned* p = &v0.x;
        #pragma unroll
        for (int q = 0; q < 4; q++) {
            float2 f = __half22float2(*reinterpret_cast<const __half2*>(&p[q]));
            acc[2*q]   += f.x * w;
            acc[2*q+1] += f.y * w;
        }
    }
    float dis = d_dis[node];         // out = D^{-1/2} A_w g2
    float4* dst = reinterpret_cast<float4*>(hout + (size_t)node * NC + sub * 8);
    dst[0] = make_float4(acc[0]*dis, acc[1]*dis, acc[2]*dis, acc[3]*dis);
    dst[1] = make_float4(acc[4]*dis, acc[5]*dis, acc[6]*dis, acc[7]*dis);
}

// ---------------- launch ------------------------------------------------------

extern "C" void kernel_launch(void* const* d_in, const int* in_sizes, int n_in,
                              void* d_out, int out_size) {
    // Resolve inputs BY ELEMENT COUNT (order-independent; all counts distinct)
    const float* x  = nullptr;
    const int*   ei = nullptr;
    const float* ew = nullptr;
    const float* W  = nullptr;
    for (int i = 0; i < n_in; i++) {
        long long sz = in_sizes[i];
        if      (sz == (long long)NN * NF) x  = (const float*)d_in[i];
        else if (sz == (long long)2 * NE)  ei = (const int*)d_in[i];
        else if (sz == (long long)NE)      ew = (const float*)d_in[i];
        else if (sz == (long long)NF * NC) W  = (const float*)d_in[i];
    }
    float* out = (float*)d_out;

    const int* row = ei;        // edge_index[0, :]
    const int* col = ei + NE;   // edge_index[1, :]

    __half* hA; cudaGetSymbolAddress((void**)&hA, d_hA);
    __half* hB; cudaGetSymbolAddress((void**)&hB, d_hB);

    // --- prep: cursor init -> W conversion -> fill (x4 ILP) -> degrees ---
    init_kernel<<<(NN + 255)/256, 256>>>();
    wconv_kernel<<<(NF * NCP + 255)/256, 256>>>(W);
    fill_kernel<<<(NE/4 + 255)/256, 256>>>(row, col, ew);
    degsum_kernel<<<(NN + 255)/256, 256>>>();

    // --- project + prescale: g0 = fp16(dis * (x @ W)) on tensor cores ---
    xw_wmma<<<(NN + 63)/64, 128>>>(x, hA);

    // --- three pull hops in g-space (6 nodes/warp, 5-lane groups) ---
    const int WARPS = (NN + 5) / 6;
    const int HOP_BLOCKS = (WARPS * 32 + 255) / 256;
    hop_h2h<<<HOP_BLOCKS, 256>>>(hA, hB);
    hop_h2h<<<HOP_BLOCKS, 256>>>(hB, hA);
    hop_h2f<<<HOP_BLOCKS, 256>>>(hA, out);
}

// round 16
// speedup vs baseline: 1.0107x; 1.0107x over previous
#include <cuda_runtime.h>
#include <cuda_fp16.h>
#include <mma.h>
#include <cstdint>

using namespace nvcuda;

// Problem constants
constexpr int NN = 100000;   // nodes
constexpr int NE = 1600000;  // edges
constexpr int NF = 128;      // input feats
constexpr int NC = 40;       // classes (post-projection feature width)
constexpr int NCP = 48;      // NC padded to 3x16 for wmma
constexpr int SLOT = 64;     // fixed per-node CSR slot (max deg ~36 for Poisson(16))

// ---------------- scratch (static device globals; no allocation) -------------
__device__ __align__(256) float  d_deg[NN];
__device__ __align__(256) float  d_invdeg[NN];
__device__ __align__(256) float  d_dis[NN];
__device__ __align__(256) int    d_cur[NN];
__device__ __align__(256) int2   d_edat[(size_t)NN * SLOT];  // (row, raw ew bits)
__device__ __align__(256) __half d_Wh[NF * NCP];             // fp16 W, N-padded
__device__ __align__(256) __half d_hA[(size_t)NN * NC];      // fp16 intermediates
__device__ __align__(256) __half d_hB[(size_t)NN * NC];

// ---------------- kernels ----------------------------------------------------

__global__ void init_kernel() {
    int i = blockIdx.x * blockDim.x + threadIdx.x;
    if (i < NN) { d_cur[i] = i * SLOT; d_deg[i] = 0.0f; }
}

// convert W[128,40] fp32 -> d_Wh[128,48] fp16 (zero-padded cols)
__global__ void wconv_kernel(const float* __restrict__ W) {
    int i = blockIdx.x * blockDim.x + threadIdx.x;
    if (i < NF * NCP) {
        int k = i / NCP, c = i % NCP;
        d_Wh[i] = __float2half((c < NC) ? W[k * NC + c] : 0.0f);
    }
}

// fixed-slot CSR fill, 4 edges/thread. Also accumulates weighted degree via
// fire-and-forget float RED (no return dependency) — kills the degsum pass.
__global__ void fill_kernel(const int* __restrict__ row,
                            const int* __restrict__ col,
                            const float* __restrict__ ew) {
    int t = blockIdx.x * blockDim.x + threadIdx.x;
    if (t >= NE / 4) return;
    int4   r4 = reinterpret_cast<const int4*>(row)[t];
    int4   c4 = reinterpret_cast<const int4*>(col)[t];
    float4 w4 = reinterpret_cast<const float4*>(ew)[t];
    const int   r[4] = {r4.x, r4.y, r4.z, r4.w};
    const int   c[4] = {c4.x, c4.y, c4.z, c4.w};
    const float w[4] = {w4.x, w4.y, w4.z, w4.w};
    int pos[4];
    #pragma unroll
    for (int u = 0; u < 4; u++) {
        bool ok = (r[u] >= 0 && r[u] < NN && c[u] >= 0 && c[u] < NN);
        pos[u] = ok ? atomicAdd(&d_cur[c[u]], 1) : -1;
        if (ok) atomicAdd(&d_deg[c[u]], w[u]);   // result unused -> REDG
    }
    #pragma unroll
    for (int u = 0; u < 4; u++) {
        if (pos[u] >= 0 && pos[u] < (c[u] + 1) * SLOT)   // overflow guard
            d_edat[pos[u]] = make_int2(r[u], __float_as_int(w[u]));
    }
}

// invdeg = 1/deg, dis = rsqrt(deg) — trivial streaming pass over d_deg.
__global__ void invdis_kernel() {
    int i = blockIdx.x * blockDim.x + threadIdx.x;
    if (i >= NN) return;
    float d = d_deg[i];
    bool pos = (d > 0.0f);
    d_invdeg[i] = pos ? (1.0f / d) : 0.0f;
    d_dis[i]    = pos ? rsqrtf(d) : 0.0f;
}

// g0[NN,40] = fp16( dis * (x[NN,128] @ W[128,40]) )  via tensor cores.
__global__ void __launch_bounds__(128) xw_wmma(const float* __restrict__ x,
                                               __half* __restrict__ y) {
    __shared__ __half sx[64][136];   // x tile, fp16, ldm=136 (mult of 8)
    __shared__ __half sw[NF][NCP];   // W, fp16
    __shared__ float  sc[64][NCP];   // fp32 epilogue buffer
    int t = threadIdx.x;
    int warp = t >> 5;
    int nb = blockIdx.x * 64;

    for (int i = t; i < NF * NCP / 2; i += 128)
        reinterpret_cast<__half2*>(&sw[0][0])[i] =
            reinterpret_cast<const __half2*>(d_Wh)[i];

    for (int i = t; i < 64 * 32; i += 128) {
        int n = i >> 5, c4 = i & 31;
        int node = nb + n;
        float4 v = (node < NN)
                 ? reinterpret_cast<const float4*>(x + (size_t)node * NF)[c4]
                 : make_float4(0.f, 0.f, 0.f, 0.f);
        *reinterpret_cast<__half2*>(&sx[n][c4 * 4])     = __floats2half2_rn(v.x, v.y);
        *reinterpret_cast<__half2*>(&sx[n][c4 * 4 + 2]) = __floats2half2_rn(v.z, v.w);
    }
    __syncthreads();

    wmma::fragment<wmma::accumulator, 16, 16, 16, float> acc[3];
    #pragma unroll
    for (int j = 0; j < 3; j++) wmma::fill_fragment(acc[j], 0.0f);

    #pragma unroll
    for (int k = 0; k < NF / 16; k++) {
        wmma::fragment<wmma::matrix_a, 16, 16, 16, __half, wmma::row_major> a;
        wmma::load_matrix_sync(a, &sx[warp * 16][k * 16], 136);
        #pragma unroll
        for (int j = 0; j < 3; j++) {
            wmma::fragment<wmma::matrix_b, 16, 16, 16, __half, wmma::row_major> b;
            wmma::load_matrix_sync(b, &sw[k * 16][j * 16], NCP);
            wmma::mma_sync(acc[j], a, b, acc[j]);
        }
    }
    #pragma unroll
    for (int j = 0; j < 3; j++)
        wmma::store_matrix_sync(&sc[warp * 16][j * 16], acc[j], NCP,
                                wmma::mem_row_major);
    __syncthreads();

    for (int i = t; i < 64 * 20; i += 128) {
        int n = i / 20, c2 = i % 20;
        int node = nb + n;
        if (node < NN) {
            float sd = d_dis[node];   // g0 = D^{-1/2}(xW)
            __half2 h = __floats2half2_rn(sc[n][c2 * 2] * sd,
                                          sc[n][c2 * 2 + 1] * sd);
            reinterpret_cast<__half2*>(y + (size_t)node * NC)[c2] = h;
        }
    }
}

// Pull hop in g-space, fp16 -> fp16: g_next[c] = invdeg[c] * sum(ew * g[row]).
// 5-lane group per node (40 halves = 5 uint4), 6 nodes/warp, unroll-4 MLP.
__global__ void hop_h2h(const __half* __restrict__ hin,
                        __half* __restrict__ hout) {
    int gwarp = (blockIdx.x * blockDim.x + threadIdx.x) >> 5;
    int ln = threadIdx.x & 31;
    if (ln >= 30) return;
    int node = gwarp * 6 + ln / 5;
    if (node >= NN) return;
    int sub = ln % 5;

    int s = node * SLOT;
    int e = d_cur[node];
    if (e > s + SLOT) e = s + SLOT;

    float acc[8] = {};
    int i = s;
    for (; i + 4 <= e; i += 4) {
        int2 ed[4];
        uint4 v[4];
        #pragma unroll
        for (int u = 0; u < 4; u++) ed[u] = d_edat[i + u];
        #pragma unroll
        for (int u = 0; u < 4; u++)
            v[u] = __ldg(reinterpret_cast<const uint4*>(hin + (size_t)ed[u].x * NC) + sub);
        #pragma unroll
        for (int u = 0; u < 4; u++) {
            float w = __int_as_float(ed[u].y);
            const unsigned* p = &v[u].x;
            #pragma unroll
            for (int q = 0; q < 4; q++) {
                float2 f = __half22float2(*reinterpret_cast<const __half2*>(&p[q]));
                acc[2*q]   += f.x * w;
                acc[2*q+1] += f.y * w;
            }
        }
    }
    for (; i < e; i++) {
        int2 e0 = d_edat[i];
        float w = __int_as_float(e0.y);
        uint4 v0 = __ldg(reinterpret_cast<const uint4*>(hin + (size_t)e0.x * NC) + sub);
        const unsigned* p = &v0.x;
        #pragma unroll
        for (int q = 0; q < 4; q++) {
            float2 f = __half22float2(*reinterpret_cast<const __half2*>(&p[q]));
            acc[2*q]   += f.x * w;
            acc[2*q+1] += f.y * w;
        }
    }
    float idg = d_invdeg[node];      // destination-side D^{-1}
    uint4 o;
    unsigned* po = &o.x;
    #pragma unroll
    for (int q = 0; q < 4; q++) {
        __half2 h = __floats2half2_rn(acc[2*q] * idg, acc[2*q+1] * idg);
        po[q] = *reinterpret_cast<unsigned*>(&h);
    }
    *(reinterpret_cast<uint4*>(hout + (size_t)node * NC) + sub) = o;
}

// Final hop, fp16 -> fp32 d_out: out[c] = dis[c] * sum(ew * g[row]).
__global__ void hop_h2f(const __half* __restrict__ hin,
                        float* __restrict__ hout) {
    int gwarp = (blockIdx.x * blockDim.x + threadIdx.x) >> 5;
    int ln = threadIdx.x & 31;
    if (ln >= 30) return;
    int node = gwarp * 6 + ln / 5;
    if (node >= NN) return;
    int sub = ln % 5;

    int s = node * SLOT;
    int e = d_cur[node];
    if (e > s + SLOT) e = s + SLOT;

    float acc[8] = {};
    int i = s;
    for (; i + 4 <= e; i += 4) {
        int2 ed[4];
        uint4 v[4];
        #pragma unroll
        for (int u = 0; u < 4; u++) ed[u] = d_edat[i + u];
        #pragma unroll
        for (int u = 0; u < 4; u++)
            v[u] = __ldg(reinterpret_cast<const uint4*>(hin + (size_t)ed[u].x * NC) + sub);
        #pragma unroll
        for (int u = 0; u < 4; u++) {
            float w = __int_as_float(ed[u].y);
            const unsigned* p = &v[u].x;
            #pragma unroll
            for (int q = 0; q < 4; q++) {
                float2 f = __half22float2(*reinterpret_cast<const __half2*>(&p[q]));
                acc[2*q]   += f.x * w;
                acc[2*q+1] += f.y * w;
            }
        }
    }
    for (; i < e; i++) {
        int2 e0 = d_edat[i];
        float w = __int_as_float(e0.y);
        uint4 v0 = __ldg(reinterpret_cast<const uint4*>(hin + (size_t)e0.x * NC) + sub);
        const unsigned* p = &v0.x;
        #pragma unroll
        for (int q = 0; q < 4; q++) {
            float2 f = __half22float2(*reinterpret_cast<const __half2*>(&p[q]));
            acc[2*q]   += f.x * w;
            acc[2*q+1] += f.y * w;
        }
    }
    float dis = d_dis[node];         // out = D^{-1/2} A_w g2
    float4* dst = reinterpret_cast<float4*>(hout + (size_t)node * NC + sub * 8);
    dst[0] = make_float4(acc[0]*dis, acc[1]*dis, acc[2]*dis, acc[3]*dis);
    dst[1] = make_float4(acc[4]*dis, acc[5]*dis, acc[6]*dis, acc[7]*dis);
}

// ---------------- launch ------------------------------------------------------

extern "C" void kernel_launch(void* const* d_in, const int* in_sizes, int n_in,
                              void* d_out, int out_size) {
    // Resolve inputs BY ELEMENT COUNT (order-independent; all counts distinct)
    const float* x  = nullptr;
    const int*   ei = nullptr;
    const float* ew = nullptr;
    const float* W  = nullptr;
    for (int i = 0; i < n_in; i++) {
        long long sz = in_sizes[i];
        if      (sz == (long long)NN * NF) x  = (const float*)d_in[i];
        else if (sz == (long long)2 * NE)  ei = (const int*)d_in[i];
        else if (sz == (long long)NE)      ew = (const float*)d_in[i];
        else if (sz == (long long)NF * NC) W  = (const float*)d_in[i];
    }
    float* out = (float*)d_out;

    const int* row = ei;        // edge_index[0, :]
    const int* col = ei + NE;   // edge_index[1, :]

    __half* hA; cudaGetSymbolAddress((void**)&hA, d_hA);
    __half* hB; cudaGetSymbolAddress((void**)&hB, d_hB);

    // --- prep: init -> W conversion -> fill (x4 ILP + deg RED) -> inv/dis ---
    init_kernel<<<(NN + 255)/256, 256>>>();
    wconv_kernel<<<(NF * NCP + 255)/256, 256>>>(W);
    fill_kernel<<<(NE/4 + 255)/256, 256>>>(row, col, ew);
    invdis_kernel<<<(NN + 255)/256, 256>>>();

    // --- project + prescale: g0 = fp16(dis * (x @ W)) on tensor cores ---
    xw_wmma<<<(NN + 63)/64, 128>>>(x, hA);

    // --- three pull hops in g-space (6 nodes/warp, 5-lane groups) ---
    const int WARPS = (NN + 5) / 6;
    const int HOP_BLOCKS = (WARPS * 32 + 255) / 256;
    hop_h2h<<<HOP_BLOCKS, 256>>>(hA, hB);
    hop_h2h<<<HOP_BLOCKS, 256>>>(hB, hA);
    hop_h2f<<<HOP_BLOCKS, 256>>>(hA, out);
}

// round 17
// speedup vs baseline: 1.0990x; 1.0875x over previous
#include <cuda_runtime.h>
#include <cuda_fp16.h>
#include <mma.h>
#include <cstdint>

using namespace nvcuda;

// Problem constants
constexpr int NN = 100000;   // nodes
constexpr int NE = 1600000;  // edges
constexpr int NF = 128;      // input feats
constexpr int NC = 40;       // classes (post-projection feature width)
constexpr int NCP = 48;      // NC padded to 3x16 for wmma
constexpr int SLOT = 64;     // fixed per-node CSR slot (max deg ~36 for Poisson(16))
constexpr float FXS = 67108864.0f;    // 2^26 fixed-point scale for degree
constexpr float FXI = 1.4901161e-8f;  // 2^-26

// ---------------- scratch (static device globals; no allocation) -------------
// d_cc[i]: high 32 bits = edge count of node i, low 32 bits = fixed-point deg.
__device__ __align__(256) unsigned long long d_cc[NN];
__device__ __align__(256) int2   d_edat[(size_t)NN * SLOT];  // (row, raw ew bits)
__device__ __align__(256) __half d_Wh[NF * NCP];             // fp16 W, N-padded
__device__ __align__(256) __half d_hA[(size_t)NN * NC];      // fp16 intermediates
__device__ __align__(256) __half d_hB[(size_t)NN * NC];

// ---------------- kernels ----------------------------------------------------

// zero packed count|deg; also convert W (fused trivial prep)
__global__ void init_kernel(const float* __restrict__ W) {
    int i = blockIdx.x * blockDim.x + threadIdx.x;
    if (i < NN) d_cc[i] = 0ull;
    if (i < NF * NCP) {
        int k = i / NCP, c = i % NCP;
        d_Wh[i] = __float2half((c < NC) ? W[k * NC + c] : 0.0f);
    }
}

// fixed-slot CSR fill, 4 edges/thread, ONE 64-bit atomic per edge:
//   +1 in the high word (cursor) and +ew*2^26 in the low word (degree).
// Return value >> 32 = slot index within the node.
__global__ void fill_kernel(const int* __restrict__ row,
                            const int* __restrict__ col,
                            const float* __restrict__ ew) {
    int t = blockIdx.x * blockDim.x + threadIdx.x;
    if (t >= NE / 4) return;
    int4   r4 = reinterpret_cast<const int4*>(row)[t];
    int4   c4 = reinterpret_cast<const int4*>(col)[t];
    float4 w4 = reinterpret_cast<const float4*>(ew)[t];
    const int   r[4] = {r4.x, r4.y, r4.z, r4.w};
    const int   c[4] = {c4.x, c4.y, c4.z, c4.w};
    const float w[4] = {w4.x, w4.y, w4.z, w4.w};
    int pos[4];
    #pragma unroll
    for (int u = 0; u < 4; u++) {
        bool ok = (r[u] >= 0 && r[u] < NN && c[u] >= 0 && c[u] < NN);
        unsigned long long add = (1ull << 32) |
            (unsigned long long)(unsigned)(w[u] * FXS);
        pos[u] = ok ? (int)(atomicAdd(&d_cc[c[u]], add) >> 32) : -1;
    }
    #pragma unroll
    for (int u = 0; u < 4; u++) {
        if (pos[u] >= 0 && pos[u] < SLOT)   // overflow guard (P ~ 1e-20)
            d_edat[(size_t)c[u] * SLOT + pos[u]] =
                make_int2(r[u], __float_as_int(w[u]));
    }
}

// g0[NN,40] = fp16( rsqrt(deg) * (x[NN,128] @ W[128,40]) )  via tensor cores.
__global__ void __launch_bounds__(128) xw_wmma(const float* __restrict__ x,
                                               __half* __restrict__ y) {
    __shared__ __half sx[64][136];   // x tile, fp16, ldm=136 (mult of 8)
    __shared__ __half sw[NF][NCP];   // W, fp16
    __shared__ float  sc[64][NCP];   // fp32 epilogue buffer
    int t = threadIdx.x;
    int warp = t >> 5;
    int nb = blockIdx.x * 64;

    for (int i = t; i < NF * NCP / 2; i += 128)
        reinterpret_cast<__half2*>(&sw[0][0])[i] =
            reinterpret_cast<const __half2*>(d_Wh)[i];

    for (int i = t; i < 64 * 32; i += 128) {
        int n = i >> 5, c4 = i & 31;
        int node = nb + n;
        float4 v = (node < NN)
                 ? reinterpret_cast<const float4*>(x + (size_t)node * NF)[c4]
                 : make_float4(0.f, 0.f, 0.f, 0.f);
        *reinterpret_cast<__half2*>(&sx[n][c4 * 4])     = __floats2half2_rn(v.x, v.y);
        *reinterpret_cast<__half2*>(&sx[n][c4 * 4 + 2]) = __floats2half2_rn(v.z, v.w);
    }
    __syncthreads();

    wmma::fragment<wmma::accumulator, 16, 16, 16, float> acc[3];
    #pragma unroll
    for (int j = 0; j < 3; j++) wmma::fill_fragment(acc[j], 0.0f);

    #pragma unroll
    for (int k = 0; k < NF / 16; k++) {
        wmma::fragment<wmma::matrix_a, 16, 16, 16, __half, wmma::row_major> a;
        wmma::load_matrix_sync(a, &sx[warp * 16][k * 16], 136);
        #pragma unroll
        for (int j = 0; j < 3; j++) {
            wmma::fragment<wmma::matrix_b, 16, 16, 16, __half, wmma::row_major> b;
            wmma::load_matrix_sync(b, &sw[k * 16][j * 16], NCP);
            wmma::mma_sync(acc[j], a, b, acc[j]);
        }
    }
    #pragma unroll
    for (int j = 0; j < 3; j++)
        wmma::store_matrix_sync(&sc[warp * 16][j * 16], acc[j], NCP,
                                wmma::mem_row_major);
    __syncthreads();

    for (int i = t; i < 64 * 20; i += 128) {
        int n = i / 20, c2 = i % 20;
        int node = nb + n;
        if (node < NN) {
            float deg = (float)(unsigned)(d_cc[node] & 0xffffffffull) * FXI;
            float sd = (deg > 0.0f) ? rsqrtf(deg) : 0.0f;  // g0 = D^{-1/2}(xW)
            __half2 h = __floats2half2_rn(sc[n][c2 * 2] * sd,
                                          sc[n][c2 * 2 + 1] * sd);
            reinterpret_cast<__half2*>(y + (size_t)node * NC)[c2] = h;
        }
    }
}

// Pull hop in g-space, fp16 -> fp16: g_next[c] = (1/deg) * sum(ew * g[row]).
// 5-lane group per node (40 halves = 5 uint4), 6 nodes/warp, unroll-4 MLP.
__global__ void hop_h2h(const __half* __restrict__ hin,
                        __half* __restrict__ hout) {
    int gwarp = (blockIdx.x * blockDim.x + threadIdx.x) >> 5;
    int ln = threadIdx.x & 31;
    if (ln >= 30) return;
    int node = gwarp * 6 + ln / 5;
    if (node >= NN) return;
    int sub = ln % 5;

    unsigned long long cc = d_cc[node];
    int cnt = (int)(cc >> 32);
    if (cnt > SLOT) cnt = SLOT;
    float deg = (float)(unsigned)(cc & 0xffffffffull) * FXI;
    float idg = (deg > 0.0f) ? (1.0f / deg) : 0.0f;

    int s = node * SLOT;
    int e = s + cnt;

    float acc[8] = {};
    int i = s;
    for (; i + 4 <= e; i += 4) {
        int2 ed[4];
        uint4 v[4];
        #pragma unroll
        for (int u = 0; u < 4; u++) ed[u] = d_edat[i + u];
        #pragma unroll
        for (int u = 0; u < 4; u++)
            v[u] = __ldg(reinterpret_cast<const uint4*>(hin + (size_t)ed[u].x * NC) + sub);
        #pragma unroll
        for (int u = 0; u < 4; u++) {
            float w = __int_as_float(ed[u].y);
            const unsigned* p = &v[u].x;
            #pragma unroll
            for (int q = 0; q < 4; q++) {
                float2 f = __half22float2(*reinterpret_cast<const __half2*>(&p[q]));
                acc[2*q]   += f.x * w;
                acc[2*q+1] += f.y * w;
            }
        }
    }
    for (; i < e; i++) {
        int2 e0 = d_edat[i];
        float w = __int_as_float(e0.y);
        uint4 v0 = __ldg(reinterpret_cast<const uint4*>(hin + (size_t)e0.x * NC) + sub);
        const unsigned* p = &v0.x;
        #pragma unroll
        for (int q = 0; q < 4; q++) {
            float2 f = __half22float2(*reinterpret_cast<const __half2*>(&p[q]));
            acc[2*q]   += f.x * w;
            acc[2*q+1] += f.y * w;
        }
    }
    uint4 o;
    unsigned* po = &o.x;
    #pragma unroll
    for (int q = 0; q < 4; q++) {
        __half2 h = __floats2half2_rn(acc[2*q] * idg, acc[2*q+1] * idg);
        po[q] = *reinterpret_cast<unsigned*>(&h);
    }
    *(reinterpret_cast<uint4*>(hout + (size_t)node * NC) + sub) = o;
}

// Final hop, fp16 -> fp32 d_out: out[c] = rsqrt(deg) * sum(ew * g[row]).
__global__ void hop_h2f(const __half* __restrict__ hin,
                        float* __restrict__ hout) {
    int gwarp = (blockIdx.x * blockDim.x + threadIdx.x) >> 5;
    int ln = threadIdx.x & 31;
    if (ln >= 30) return;
    int node = gwarp * 6 + ln / 5;
    if (node >= NN) return;
    int sub = ln % 5;

    unsigned long long cc = d_cc[node];
    int cnt = (int)(cc >> 32);
    if (cnt > SLOT) cnt = SLOT;
    float deg = (float)(unsigned)(cc & 0xffffffffull) * FXI;
    float dis = (deg > 0.0f) ? rsqrtf(deg) : 0.0f;

    int s = node * SLOT;
    int e = s + cnt;

    float acc[8] = {};
    int i = s;
    for (; i + 4 <= e; i += 4) {
        int2 ed[4];
        uint4 v[4];
        #pragma unroll
        for (int u = 0; u < 4; u++) ed[u] = d_edat[i + u];
        #pragma unroll
        for (int u = 0; u < 4; u++)
            v[u] = __ldg(reinterpret_cast<const uint4*>(hin + (size_t)ed[u].x * NC) + sub);
        #pragma unroll
        for (int u = 0; u < 4; u++) {
            float w = __int_as_float(ed[u].y);
            const unsigned* p = &v[u].x;
            #pragma unroll
            for (int q = 0; q < 4; q++) {
                float2 f = __half22float2(*reinterpret_cast<const __half2*>(&p[q]));
                acc[2*q]   += f.x * w;
                acc[2*q+1] += f.y * w;
            }
        }
    }
    for (; i < e; i++) {
        int2 e0 = d_edat[i];
        float w = __int_as_float(e0.y);
        uint4 v0 = __ldg(reinterpret_cast<const uint4*>(hin + (size_t)e0.x * NC) + sub);
        const unsigned* p = &v0.x;
        #pragma unroll
        for (int q = 0; q < 4; q++) {
            float2 f = __half22float2(*reinterpret_cast<const __half2*>(&p[q]));
            acc[2*q]   += f.x * w;
            acc[2*q+1] += f.y * w;
        }
    }
    float4* dst = reinterpret_cast<float4*>(hout + (size_t)node * NC + sub * 8);
    dst[0] = make_float4(acc[0]*dis, acc[1]*dis, acc[2]*dis, acc[3]*dis);
    dst[1] = make_float4(acc[4]*dis, acc[5]*dis, acc[6]*dis, acc[7]*dis);
}

// ---------------- launch ------------------------------------------------------

extern "C" void kernel_launch(void* const* d_in, const int* in_sizes, int n_in,
                              void* d_out, int out_size) {
    // Resolve inputs BY ELEMENT COUNT (order-independent; all counts distinct)
    const float* x  = nullptr;
    const int*   ei = nullptr;
    const float* ew = nullptr;
    const float* W  = nullptr;
    for (int i = 0; i < n_in; i++) {
        long long sz = in_sizes[i];
        if      (sz == (long long)NN * NF) x  = (const float*)d_in[i];
        else if (sz == (long long)2 * NE)  ei = (const int*)d_in[i];
        else if (sz == (long long)NE)      ew = (const float*)d_in[i];
        else if (sz == (long long)NF * NC) W  = (const float*)d_in[i];
    }
    float* out = (float*)d_out;

    const int* row = ei;        // edge_index[0, :]
    const int* col = ei + NE;   // edge_index[1, :]

    __half* hA; cudaGetSymbolAddress((void**)&hA, d_hA);
    __half* hB; cudaGetSymbolAddress((void**)&hB, d_hB);

    // --- prep: init (cc zero + W convert) -> fill (1 packed atomic/edge) ---
    init_kernel<<<(NN + 255)/256, 256>>>(W);
    fill_kernel<<<(NE/4 + 255)/256, 256>>>(row, col, ew);

    // --- project + prescale: g0 = fp16(rsqrt(deg) * (x @ W)) on tensor cores ---
    xw_wmma<<<(NN + 63)/64, 128>>>(x, hA);

    // --- three pull hops in g-space (6 nodes/warp, 5-lane groups) ---
    const int WARPS = (NN + 5) / 6;
    const int HOP_BLOCKS = (WARPS * 32 + 255) / 256;
    hop_h2h<<<HOP_BLOCKS, 256>>>(hA, hB);
    hop_h2h<<<HOP_BLOCKS, 256>>>(hB, hA);
    hop_h2f<<<HOP_BLOCKS, 256>>>(hA, out);
}